// round 4
// baseline (speedup 1.0000x reference)
#include <cuda_runtime.h>
#include <cuda_bf16.h>
#include <cstdint>

#define NVERT   16384
#define OCOLS   1024                     // columns per slice
#define NSLICE  (NVERT / OCOLS)          // 16
#define RQUADS  (NVERT / 4)              // 4096 row-quads
#define NUNITS  (RQUADS * NSLICE)        // 65536
#define BLOCK   1024
#define MAXGRID 512
#define SMEM_BYTES (3 * NVERT * sizeof(float))   // 196608 B

// Deterministic partial sums: y[slice][row][comp]  (16 * 16384 * 3 floats = 3 MB)
__device__ float g_y[NSLICE * NVERT * 3];
// Per-block loss partials (fixed slice per block -> deterministic)
__device__ float g_part[MAXGRID];
// Work-stealing + barrier state (reset by block 0 at end of each run)
__device__ unsigned int g_ticket = 0;
__device__ unsigned int g_bar1   = 0;
__device__ unsigned int g_bar2   = 0;

__device__ __forceinline__ float block_reduce(float s, float* red) {
    const int lane = threadIdx.x & 31;
    const int wid  = threadIdx.x >> 5;
    #pragma unroll
    for (int off = 16; off > 0; off >>= 1)
        s += __shfl_xor_sync(0xFFFFFFFFu, s, off);
    if (lane == 0) red[wid] = s;
    __syncthreads();
    float t = 0.f;
    if (wid == 0) {
        t = (lane < (BLOCK >> 5)) ? red[lane] : 0.f;
        #pragma unroll
        for (int off = 16; off > 0; off >>= 1)
            t += __shfl_xor_sync(0xFFFFFFFFu, t, off);
    }
    return t;   // valid in warp 0
}

__global__ void __launch_bounds__(BLOCK, 1)
lap_fused_kernel(const float* __restrict__ L, const float* __restrict__ x,
                 float* __restrict__ out) {
    extern __shared__ float sx[];   // SoA: [3][NVERT]
    __shared__ float red[32];

    // Stage x into shared memory: SoA, per-vertex
    for (int vert = threadIdx.x; vert < NVERT; vert += BLOCK) {
        float a = x[3 * vert + 0];
        float b = x[3 * vert + 1];
        float c = x[3 * vert + 2];
        sx[0 * NVERT + vert] = a;
        sx[1 * NVERT + vert] = b;
        sx[2 * NVERT + vert] = c;
    }
    __syncthreads();

    const int lane = threadIdx.x & 31;

    // ---------------- Phase 1: stream L with work stealing ----------------
    // Unit = 4 rows x 1024 columns (16 KB of L). 3 smem loads per 4 global
    // loads (0.75x smem:dram byte ratio).
    for (;;) {
        unsigned int u;
        if (lane == 0) u = atomicAdd(&g_ticket, 1u);
        u = __shfl_sync(0xFFFFFFFFu, u, 0);
        if (u >= NUNITS) break;

        const int p = (int)(u >> 4);            // row quad -> rows 4p..4p+3
        const int o = (int)(u & (NSLICE - 1));  // column slice

        const float4* __restrict__ rb =
            (const float4*)(L + (size_t)(4 * p) * NVERT) + o * (OCOLS / 4);
        const int rstride = NVERT / 4;          // row stride in float4

        const float4* __restrict__ xs0 = (const float4*)(sx + 0 * NVERT + o * OCOLS);
        const float4* __restrict__ xs1 = (const float4*)(sx + 1 * NVERT + o * OCOLS);
        const float4* __restrict__ xs2 = (const float4*)(sx + 2 * NVERT + o * OCOLS);

        float acc[12];
        #pragma unroll
        for (int j = 0; j < 12; j++) acc[j] = 0.f;

        #pragma unroll 4
        for (int i = lane; i < OCOLS / 4; i += 32) {
            float4 l0 = __ldcs(rb + 0 * rstride + i);   // streaming, zero reuse
            float4 l1 = __ldcs(rb + 1 * rstride + i);
            float4 l2 = __ldcs(rb + 2 * rstride + i);
            float4 l3 = __ldcs(rb + 3 * rstride + i);
            float4 v0 = xs0[i];
            float4 v1 = xs1[i];
            float4 v2 = xs2[i];

            acc[0]  += l0.x * v0.x + l0.y * v0.y + l0.z * v0.z + l0.w * v0.w;
            acc[1]  += l0.x * v1.x + l0.y * v1.y + l0.z * v1.z + l0.w * v1.w;
            acc[2]  += l0.x * v2.x + l0.y * v2.y + l0.z * v2.z + l0.w * v2.w;
            acc[3]  += l1.x * v0.x + l1.y * v0.y + l1.z * v0.z + l1.w * v0.w;
            acc[4]  += l1.x * v1.x + l1.y * v1.y + l1.z * v1.z + l1.w * v1.w;
            acc[5]  += l1.x * v2.x + l1.y * v2.y + l1.z * v2.z + l1.w * v2.w;
            acc[6]  += l2.x * v0.x + l2.y * v0.y + l2.z * v0.z + l2.w * v0.w;
            acc[7]  += l2.x * v1.x + l2.y * v1.y + l2.z * v1.z + l2.w * v1.w;
            acc[8]  += l2.x * v2.x + l2.y * v2.y + l2.z * v2.z + l2.w * v2.w;
            acc[9]  += l3.x * v0.x + l3.y * v0.y + l3.z * v0.z + l3.w * v0.w;
            acc[10] += l3.x * v1.x + l3.y * v1.y + l3.z * v1.z + l3.w * v1.w;
            acc[11] += l3.x * v2.x + l3.y * v2.y + l3.z * v2.z + l3.w * v2.w;
        }

        #pragma unroll
        for (int j = 0; j < 12; j++) {
            #pragma unroll
            for (int off = 16; off > 0; off >>= 1)
                acc[j] += __shfl_xor_sync(0xFFFFFFFFu, acc[j], off);
        }

        if (lane < 12) {
            float v = 0.f;
            #pragma unroll
            for (int j = 0; j < 12; j++)
                if (lane == j) v = acc[j];
            const int r   = lane / 3;           // 0..3
            const int c   = lane - 3 * r;       // 0..2
            const int row = 4 * p + r;
            g_y[(o * NVERT + row) * 3 + c] = v;
        }
    }

    // ---------------- Grid barrier 1 (all blocks co-resident: grid == #SMs) ----
    __syncthreads();
    if (threadIdx.x == 0) {
        __threadfence();                       // publish g_y writes
        atomicAdd(&g_bar1, 1u);
        while (*(volatile unsigned int*)&g_bar1 < gridDim.x) { }
        __threadfence();                       // acquire
    }
    __syncthreads();

    // ---------------- Phase 2: parallel deterministic reduction ----------------
    // g_y viewed as NSLICE slices of 12288 float4 each (L2-resident).
    {
        const float4* __restrict__ yv = (const float4*)g_y;
        const int total = (NVERT * 3) / 4;                       // 12288
        const int per   = (total + gridDim.x - 1) / gridDim.x;
        const int base  = blockIdx.x * per;
        const int end   = (base + per < total) ? (base + per) : total;

        float s = 0.f;
        for (int i = base + threadIdx.x; i < end; i += BLOCK) {
            float4 a = yv[i];
            #pragma unroll
            for (int j = 1; j < NSLICE; j++) {
                float4 b = yv[i + j * total];
                a.x += b.x; a.y += b.y; a.z += b.z; a.w += b.w;
            }
            s += a.x * a.x + a.y * a.y + a.z * a.z + a.w * a.w;
        }
        float t = block_reduce(s, red);
        if (threadIdx.x == 0) {
            g_part[blockIdx.x] = t;
            __threadfence();
            atomicAdd(&g_bar2, 1u);
        }
    }

    // ---------------- Block 0 finalizes + resets state ----------------
    if (blockIdx.x == 0) {
        if (threadIdx.x == 0) {
            while (*(volatile unsigned int*)&g_bar2 < gridDim.x) { }
            __threadfence();
        }
        __syncthreads();

        float s = (threadIdx.x < gridDim.x) ? g_part[threadIdx.x] : 0.f;
        float t = block_reduce(s, red);
        if (threadIdx.x == 0) {
            out[0]   = t;
            g_ticket = 0;     // safe: every block has passed barrier 1 & 2
            g_bar1   = 0;
            g_bar2   = 0;
            __threadfence();
        }
    }
}

extern "C" void kernel_launch(void* const* d_in, const int* in_sizes, int n_in,
                              void* d_out, int out_size) {
    // Identify inputs by element count: x has NVERT*3, L has NVERT*NVERT.
    const float* x = (const float*)d_in[0];
    const float* L = (const float*)d_in[1];
    if (in_sizes[0] != NVERT * 3) {
        x = (const float*)d_in[1];
        L = (const float*)d_in[0];
    }
    float* out = (float*)d_out;

    // Grid = #SMs -> 1 resident CTA per SM (1024 thr + 192KB smem), making the
    // in-kernel grid spin-barrier deadlock-free on any SKU.
    int dev = 0;
    cudaGetDevice(&dev);
    int sms = 148;
    cudaDeviceGetAttribute(&sms, cudaDevAttrMultiProcessorCount, dev);
    if (sms < 1) sms = 1;
    if (sms > MAXGRID) sms = MAXGRID;

    cudaFuncSetAttribute(lap_fused_kernel,
                         cudaFuncAttributeMaxDynamicSharedMemorySize,
                         (int)SMEM_BYTES);

    lap_fused_kernel<<<sms, BLOCK, SMEM_BYTES>>>(L, x, out);
}

// round 5
// speedup vs baseline: 1.4693x; 1.4693x over previous
#include <cuda_runtime.h>
#include <cuda_bf16.h>
#include <cstdint>

#define NVERT    16384
#define BLOCK    1024
#define GRID     148
#define NWARPS   (GRID * (BLOCK / 32))
#define SMEM_BYTES (3 * NVERT * sizeof(float))   // 196608 B

// Tier A: row-pairs 0..7679, units = pair x 4 quarters of 4096 cols (32 KB)
#define A_PAIRS   7680
#define A_UNITS   (A_PAIRS * 4)          // 30720
#define A_COLS    4096
// Tier B: row-pairs 7680..8191, units = pair x 16 slices of 1024 cols (8 KB)
#define B_PAIRS   512
#define B_ROW0    (2 * A_PAIRS)          // 15360
#define B_UNITS   (B_PAIRS * 16)         // 8192
#define B_COLS    1024
#define NUNITS    (A_UNITS + B_UNITS)    // 38912

// Deterministic partials.
// Tier A rows: y4[q][row][comp], rows 0..15359 used.
__device__ float g_y4[4 * NVERT * 3];
// Tier B rows: y16[s][lrow][comp], lrow = row - 15360 (0..1023).
__device__ float g_y16[16 * (2 * B_PAIRS) * 3];
// Work-stealing state (self-resetting for graph replays)
__device__ unsigned int g_ticket = 0;
__device__ unsigned int g_done   = 0;

__global__ void __launch_bounds__(BLOCK, 1)
lap_main_kernel(const float* __restrict__ L, const float* __restrict__ x,
                float* __restrict__ out) {
    extern __shared__ float sx[];   // SoA: [3][NVERT]

    if (blockIdx.x == 0 && threadIdx.x == 0) out[0] = 0.0f;

    // Stage x into shared memory: SoA, per-vertex
    for (int vert = threadIdx.x; vert < NVERT; vert += BLOCK) {
        float a = x[3 * vert + 0];
        float b = x[3 * vert + 1];
        float c = x[3 * vert + 2];
        sx[0 * NVERT + vert] = a;
        sx[1 * NVERT + vert] = b;
        sx[2 * NVERT + vert] = c;
    }
    __syncthreads();

    const int lane = threadIdx.x & 31;

    for (;;) {
        unsigned int u;
        if (lane == 0) u = atomicAdd(&g_ticket, 1u);
        u = __shfl_sync(0xFFFFFFFFu, u, 0);
        if (u >= NUNITS) break;

        int row0, colbase, niter;   // unit geometry
        if (u < A_UNITS) {
            const int p = (int)(u >> 2);
            const int q = (int)(u & 3);
            row0 = 2 * p;
            colbase = q * A_COLS;
            niter = A_COLS / 4;
        } else {
            const unsigned int t = u - A_UNITS;
            const int p = (int)(t >> 4);
            const int s = (int)(t & 15);
            row0 = B_ROW0 + 2 * p;
            colbase = s * B_COLS;
            niter = B_COLS / 4;
        }

        const float4* __restrict__ r0 =
            (const float4*)(L + (size_t)row0 * NVERT + colbase);
        const float4* __restrict__ r1 = r0 + (NVERT / 4);

        const float4* __restrict__ xs0 = (const float4*)(sx + 0 * NVERT + colbase);
        const float4* __restrict__ xs1 = (const float4*)(sx + 1 * NVERT + colbase);
        const float4* __restrict__ xs2 = (const float4*)(sx + 2 * NVERT + colbase);

        float a00 = 0.f, a01 = 0.f, a02 = 0.f;
        float a10 = 0.f, a11 = 0.f, a12 = 0.f;

        #pragma unroll 4
        for (int i = lane; i < niter; i += 32) {
            float4 l0 = __ldcs(r0 + i);   // streaming: L has zero reuse
            float4 l1 = __ldcs(r1 + i);
            float4 v0 = xs0[i];
            float4 v1 = xs1[i];
            float4 v2 = xs2[i];

            a00 += l0.x * v0.x + l0.y * v0.y + l0.z * v0.z + l0.w * v0.w;
            a01 += l0.x * v1.x + l0.y * v1.y + l0.z * v1.z + l0.w * v1.w;
            a02 += l0.x * v2.x + l0.y * v2.y + l0.z * v2.z + l0.w * v2.w;
            a10 += l1.x * v0.x + l1.y * v0.y + l1.z * v0.z + l1.w * v0.w;
            a11 += l1.x * v1.x + l1.y * v1.y + l1.z * v1.z + l1.w * v1.w;
            a12 += l1.x * v2.x + l1.y * v2.y + l1.z * v2.z + l1.w * v2.w;
        }

        #pragma unroll
        for (int off = 16; off > 0; off >>= 1) {
            a00 += __shfl_xor_sync(0xFFFFFFFFu, a00, off);
            a01 += __shfl_xor_sync(0xFFFFFFFFu, a01, off);
            a02 += __shfl_xor_sync(0xFFFFFFFFu, a02, off);
            a10 += __shfl_xor_sync(0xFFFFFFFFu, a10, off);
            a11 += __shfl_xor_sync(0xFFFFFFFFu, a11, off);
            a12 += __shfl_xor_sync(0xFFFFFFFFu, a12, off);
        }

        if (lane < 6) {
            float v;
            switch (lane) {
                case 0: v = a00; break;
                case 1: v = a01; break;
                case 2: v = a02; break;
                case 3: v = a10; break;
                case 4: v = a11; break;
                default: v = a12; break;
            }
            const int row = row0 + (lane >= 3 ? 1 : 0);
            const int c   = (lane >= 3) ? (lane - 3) : lane;
            if (u < A_UNITS) {
                const int q = (int)(u & 3);
                g_y4[(q * NVERT + row) * 3 + c] = v;
            } else {
                const int s = (int)((u - A_UNITS) & 15);
                g_y16[(s * (2 * B_PAIRS) + (row - B_ROW0)) * 3 + c] = v;
            }
        }
    }

    // Self-reset: last warp restores counters for the next graph replay.
    if (lane == 0) {
        __threadfence();
        unsigned int d = atomicAdd(&g_done, 1u);
        if (d == NWARPS - 1) {
            g_ticket = 0;
            g_done   = 0;
            __threadfence();
        }
    }
}

__global__ void pass2_kernel(float* __restrict__ out) {
    __shared__ float red[32];
    float s = 0.f;
    const int stride = gridDim.x * blockDim.x;
    const int tid = blockIdx.x * blockDim.x + threadIdx.x;

    // Tier A region: rows 0..15359 -> 15360*3/4 = 11520 float4 per slice.
    {
        const float4* __restrict__ yv = (const float4*)g_y4;
        const int totalA = (B_ROW0 * 3) / 4;             // 11520
        const int sliceStride = (NVERT * 3) / 4;         // 12288 (q-slice stride)
        for (int i = tid; i < totalA; i += stride) {
            float4 a = yv[i];
            float4 b = yv[i + sliceStride];
            float4 c = yv[i + 2 * sliceStride];
            float4 d = yv[i + 3 * sliceStride];
            float vx = a.x + b.x + c.x + d.x;
            float vy = a.y + b.y + c.y + d.y;
            float vz = a.z + b.z + c.z + d.z;
            float vw = a.w + b.w + c.w + d.w;
            s += vx * vx + vy * vy + vz * vz + vw * vw;
        }
    }
    // Tier B region: 1024 rows -> 1024*3/4 = 768 float4 per slice, 16 slices.
    {
        const float4* __restrict__ yv = (const float4*)g_y16;
        const int totalB = (2 * B_PAIRS * 3) / 4;        // 768
        for (int i = tid; i < totalB; i += stride) {
            float4 a = yv[i];
            #pragma unroll
            for (int j = 1; j < 16; j++) {
                float4 b = yv[i + j * totalB];
                a.x += b.x; a.y += b.y; a.z += b.z; a.w += b.w;
            }
            s += a.x * a.x + a.y * a.y + a.z * a.z + a.w * a.w;
        }
    }

    #pragma unroll
    for (int off = 16; off > 0; off >>= 1)
        s += __shfl_xor_sync(0xFFFFFFFFu, s, off);
    const int lane = threadIdx.x & 31;
    const int wid  = threadIdx.x >> 5;
    if (lane == 0) red[wid] = s;
    __syncthreads();
    if (wid == 0) {
        int nwarps = blockDim.x >> 5;
        float t = (lane < nwarps) ? red[lane] : 0.f;
        #pragma unroll
        for (int off = 16; off > 0; off >>= 1)
            t += __shfl_xor_sync(0xFFFFFFFFu, t, off);
        if (lane == 0) atomicAdd(out, t);
    }
}

extern "C" void kernel_launch(void* const* d_in, const int* in_sizes, int n_in,
                              void* d_out, int out_size) {
    // Identify inputs by element count: x has NVERT*3, L has NVERT*NVERT.
    const float* x = (const float*)d_in[0];
    const float* L = (const float*)d_in[1];
    if (in_sizes[0] != NVERT * 3) {
        x = (const float*)d_in[1];
        L = (const float*)d_in[0];
    }
    float* out = (float*)d_out;

    cudaFuncSetAttribute(lap_main_kernel,
                         cudaFuncAttributeMaxDynamicSharedMemorySize,
                         (int)SMEM_BYTES);

    lap_main_kernel<<<GRID, BLOCK, SMEM_BYTES>>>(L, x, out);
    pass2_kernel<<<96, 256>>>(out);
}